// round 7
// baseline (speedup 1.0000x reference)
#include <cuda_runtime.h>
#include <cuda_bf16.h>

#define KNB 32
#define CUTOFF 5.0f
#define INVALID_KEY 0xFFFFFFFFFFFFFFFFull
#define FULLMASK 0xFFFFFFFFu

// XLA-matching sum of squares: rn(rn(rn(x^2)+rn(y^2))+rn(z^2)), NO fma fusion
__device__ __forceinline__ float sumsq_xla(float x, float y, float z) {
    return __fadd_rn(__fadd_rn(__fmul_rn(x, x), __fmul_rn(y, y)), __fmul_rn(z, z));
}

__device__ __forceinline__ unsigned long long shfl_xor64(unsigned long long v, int m) {
    return __shfl_xor_sync(FULLMASK, v, m);
}
__device__ __forceinline__ unsigned long long shfl_idx64(unsigned long long v, int s) {
    return __shfl_sync(FULLMASK, v, s);
}
__device__ __forceinline__ unsigned long long shfl_up64(unsigned long long v) {
    return __shfl_up_sync(FULLMASK, v, 1);
}

// full bitonic sort of 32 keys (one per lane), ascending by lane
__device__ __forceinline__ void bitonic_sort32(unsigned long long& v, int lane) {
#pragma unroll
    for (int k = 2; k <= 32; k <<= 1) {
#pragma unroll
        for (int j = k >> 1; j > 0; j >>= 1) {
            unsigned long long o = shfl_xor64(v, j);
            bool up = ((lane & k) == 0);
            bool takeMin = (((lane & j) == 0) == up);
            if ((o < v) == takeMin) v = o;
        }
    }
}

// insert key k into sorted-ascending L (drops old max). No-op if k >= L[31].
__device__ __forceinline__ void warp_insert(unsigned long long& L,
                                            unsigned long long k, int lane) {
    unsigned mask_lt = __ballot_sync(FULLMASK, L < k);
    int p = __popc(mask_lt);                 // insertion position
    unsigned long long Ls = shfl_up64(L);    // L[lane-1]
    if (lane >= p) L = (lane == p) ? k : Ls; // lanes < p unchanged
}

// insert all candidates whose ballot bits are set, skipping the first `skip` ranks
__device__ __forceinline__ void insert_ballot(unsigned long long& L,
                                              unsigned long long& thresh,
                                              unsigned long long key,
                                              unsigned bal, int skip, int lane) {
    for (int q = 0; q < skip && bal; q++) bal &= bal - 1;
    while (bal) {
        int s = __ffs(bal) - 1;
        bal &= bal - 1;
        unsigned long long k = shfl_idx64(key, s);
        if (k < thresh) {
            warp_insert(L, k, lane);
            thresh = shfl_idx64(L, 31);
        }
    }
}

__global__ void __launch_bounds__(64)
radius_graph_kernel(const float* __restrict__ pos,
                    const int* __restrict__ batch,
                    float* __restrict__ out,
                    int N) {
    int w = (int)((blockIdx.x * blockDim.x + threadIdx.x) >> 5);
    int lane = threadIdx.x & 31;
    const int i0 = 2 * w;
    if (i0 >= N) return;
    const int i1 = i0 + 1;
    const bool has1 = (i1 < N);
    const int nk = N * KNB;

    const float x0 = pos[3 * i0 + 0], y0 = pos[3 * i0 + 1], z0 = pos[3 * i0 + 2];
    const float sq0 = sumsq_xla(x0, y0, z0);
    const int b0 = batch[i0];

    float x1 = x0, y1 = y0, z1 = z0, sq1 = sq0;
    int b1 = b0;
    if (has1) {
        x1 = pos[3 * i1 + 0]; y1 = pos[3 * i1 + 1]; z1 = pos[3 * i1 + 2];
        sq1 = sumsq_xla(x1, y1, z1);
        b1 = batch[i1];
    }

    // LO = first index of molecule b0; HI = one past last of molecule b1
    int LO, HI;
    {
        int l = 0, r = N;
        while (l < r) { int m = (l + r) >> 1; if (batch[m] < b0) l = m + 1; else r = m; }
        LO = l;
    }
    {
        int l = LO, r = N;
        while (l < r) { int m = (l + r) >> 1; if (batch[m] <= b1) l = m + 1; else r = m; }
        HI = l;
    }
    int hi0 = (b0 == b1) ? HI : i1;   // batch sorted: split exactly at i1
    int lo1 = (b0 == b1) ? LO : i1;

    unsigned long long L0 = INVALID_KEY, L1 = INVALID_KEY;
    unsigned long long P0 = INVALID_KEY, P1 = INVALID_KEY;
    unsigned long long th0 = INVALID_KEY, th1 = INVALID_KEY;
    int cnt0 = 0, cnt1 = 0;
    bool full0 = false, full1 = false;

    const int per = (HI - LO + 31) >> 5;
    for (int t = 0; t < per; t++) {
        int j = LO + lane + (t << 5);
        unsigned long long key0 = INVALID_KEY, key1 = INVALID_KEY;
        if (j < HI) {
            float xj = pos[3 * j + 0];
            float yj = pos[3 * j + 1];
            float zj = pos[3 * j + 2];
            float sqj = sumsq_xla(xj, yj, zj);
            if (j < hi0 && j != i0) {
                float dot = __fmaf_rn(z0, zj, __fmaf_rn(y0, yj, __fmul_rn(x0, xj)));
                float d2 = __fsub_rn(__fadd_rn(sq0, sqj), __fmul_rn(2.0f, dot));
                float dist = __fsqrt_rn(fmaxf(d2, 0.0f));
                if (dist <= CUTOFF) {
                    unsigned long long k64 =
                        (((unsigned long long)__float_as_uint(dist)) << 32) | (unsigned int)j;
                    if (k64 < th0) key0 = k64;
                }
            }
            if (has1 && j >= lo1 && j != i1) {
                float dot = __fmaf_rn(z1, zj, __fmaf_rn(y1, yj, __fmul_rn(x1, xj)));
                float d2 = __fsub_rn(__fadd_rn(sq1, sqj), __fmul_rn(2.0f, dot));
                float dist = __fsqrt_rn(fmaxf(d2, 0.0f));
                if (dist <= CUTOFF) {
                    unsigned long long k64 =
                        (((unsigned long long)__float_as_uint(dist)) << 32) | (unsigned int)j;
                    if (k64 < th1) key1 = k64;
                }
            }
        }
        unsigned bal0 = __ballot_sync(FULLMASK, key0 != INVALID_KEY);
        unsigned bal1 = __ballot_sync(FULLMASK, key1 != INVALID_KEY);

        if (bal0) {
            if (!full0) {
                int nv = __popc(bal0), space = 32 - cnt0;
                int r = lane - cnt0;
                unsigned src = __fns(bal0, 0, r + 1);
                unsigned long long moved = shfl_idx64(key0, (int)(src & 31u));
                if (r >= 0 && r < nv && r < space) P0 = moved;
                if (nv >= space) {
                    bitonic_sort32(P0, lane);
                    L0 = P0; full0 = true;
                    th0 = shfl_idx64(L0, 31);
                    insert_ballot(L0, th0, key0, bal0, space, lane);
                } else cnt0 += nv;
            } else {
                insert_ballot(L0, th0, key0, bal0, 0, lane);
            }
        }
        if (bal1) {
            if (!full1) {
                int nv = __popc(bal1), space = 32 - cnt1;
                int r = lane - cnt1;
                unsigned src = __fns(bal1, 0, r + 1);
                unsigned long long moved = shfl_idx64(key1, (int)(src & 31u));
                if (r >= 0 && r < nv && r < space) P1 = moved;
                if (nv >= space) {
                    bitonic_sort32(P1, lane);
                    L1 = P1; full1 = true;
                    th1 = shfl_idx64(L1, 31);
                    insert_ballot(L1, th1, key1, bal1, space, lane);
                } else cnt1 += nv;
            } else {
                insert_ballot(L1, th1, key1, bal1, 0, lane);
            }
        }
    }
    // molecules with <32 valid candidates never went full: sort partial buffer
    if (!full0 && cnt0 > 0) { bitonic_sort32(P0, lane); L0 = P0; }
    if (!full1 && cnt1 > 0) { bitonic_sort32(P1, lane); L1 = P1; }

    // lane k owns output slot k: k-th nearest neighbor (exact top_k order)
    {
        const bool valid = (L0 != INVALID_KEY);
        const int j = valid ? (int)(unsigned int)(L0 & 0xFFFFFFFFull) : i0;
        const int e = i0 * KNB + lane;
        float vx = 0.0f, vy = 0.0f, vz = 0.0f;
        if (valid) {
            vx = __fsub_rn(pos[3 * j + 0], x0);
            vy = __fsub_rn(pos[3 * j + 1], y0);
            vz = __fsub_rn(pos[3 * j + 2], z0);
        }
        out[e]                  = (float)i0;
        out[nk + e]             = (float)j;
        out[2 * nk + 3 * e + 0] = vx;
        out[2 * nk + 3 * e + 1] = vy;
        out[2 * nk + 3 * e + 2] = vz;
        out[5 * nk + e]         = valid ? 1.0f : 0.0f;
    }
    if (has1) {
        const bool valid = (L1 != INVALID_KEY);
        const int j = valid ? (int)(unsigned int)(L1 & 0xFFFFFFFFull) : i1;
        const int e = i1 * KNB + lane;
        float vx = 0.0f, vy = 0.0f, vz = 0.0f;
        if (valid) {
            vx = __fsub_rn(pos[3 * j + 0], x1);
            vy = __fsub_rn(pos[3 * j + 1], y1);
            vz = __fsub_rn(pos[3 * j + 2], z1);
        }
        out[e]                  = (float)i1;
        out[nk + e]             = (float)j;
        out[2 * nk + 3 * e + 0] = vx;
        out[2 * nk + 3 * e + 1] = vy;
        out[2 * nk + 3 * e + 2] = vz;
        out[5 * nk + e]         = valid ? 1.0f : 0.0f;
    }
}

extern "C" void kernel_launch(void* const* d_in, const int* in_sizes, int n_in,
                              void* d_out, int out_size) {
    const float* pos = (const float*)d_in[0];
    const int* batch = (const int*)d_in[1];
    float* out = (float*)d_out;
    int N = in_sizes[1];            // batch has one entry per atom
    (void)n_in; (void)out_size;

    int nwarps = (N + 1) / 2;       // two atoms per warp
    const int warpsPerBlock = 2;    // 64 threads: finer CTA balance over 148 SMs
    int blocks = (nwarps + warpsPerBlock - 1) / warpsPerBlock;
    radius_graph_kernel<<<blocks, warpsPerBlock * 32>>>(pos, batch, out, N);
}

// round 8
// speedup vs baseline: 1.0198x; 1.0198x over previous
#include <cuda_runtime.h>
#include <cuda_bf16.h>

#define KNB 32
#define CUTOFF 5.0f
#define INVALID_KEY 0xFFFFFFFFFFFFFFFFull
#define FULLMASK 0xFFFFFFFFu

// XLA-matching sum of squares: rn(rn(rn(x^2)+rn(y^2))+rn(z^2)), NO fma fusion
__device__ __forceinline__ float sumsq_xla(float x, float y, float z) {
    return __fadd_rn(__fadd_rn(__fmul_rn(x, x), __fmul_rn(y, y)), __fmul_rn(z, z));
}

__device__ __forceinline__ unsigned long long shfl_xor64(unsigned long long v, int m) {
    return __shfl_xor_sync(FULLMASK, v, m);
}
__device__ __forceinline__ unsigned long long shfl_idx64(unsigned long long v, int s) {
    return __shfl_sync(FULLMASK, v, s);
}

// full bitonic sort of 32 keys (one per lane), ascending by lane
__device__ __forceinline__ void bitonic_sort32(unsigned long long& v, int lane) {
#pragma unroll
    for (int k = 2; k <= 32; k <<= 1) {
#pragma unroll
        for (int j = k >> 1; j > 0; j >>= 1) {
            unsigned long long o = shfl_xor64(v, j);
            bool up = ((lane & k) == 0);
            bool takeMin = (((lane & j) == 0) == up);
            if ((o < v) == takeMin) v = o;
        }
    }
}

// bitonic merge (input bitonic), sorts ascending by lane
__device__ __forceinline__ void bitonic_merge32(unsigned long long& v, int lane) {
#pragma unroll
    for (int j = 16; j > 0; j >>= 1) {
        unsigned long long o = shfl_xor64(v, j);
        bool takeMin = ((lane & j) == 0);
        if ((o < v) == takeMin) v = o;
    }
}

// accumulate ballot'd candidates into compaction buffer P; flush into L when full
__device__ __forceinline__ void accum(unsigned long long& L, unsigned long long& P,
                                      int& cnt, unsigned long long& thresh, bool& first,
                                      unsigned long long key, unsigned bal, int lane) {
    int nv = __popc(bal);
    int space = 32 - cnt;
    int r = lane - cnt;
    unsigned src = __fns(bal, 0, r + 1);
    unsigned long long moved = shfl_idx64(key, (int)(src & 31u));
    if (r >= 0 && r < nv && r < space) P = moved;

    if (nv >= space) {
        bitonic_sort32(P, lane);
        if (first) {
            L = P; first = false;
        } else {
            unsigned long long brev = shfl_xor64(P, 31);
            L = (L < brev) ? L : brev;
            bitonic_merge32(L, lane);
        }
        thresh = shfl_idx64(L, 31);
        int nv2 = nv - space;
        unsigned src2 = __fns(bal, 0, lane + space + 1);
        unsigned long long moved2 = shfl_idx64(key, (int)(src2 & 31u));
        P = (lane < nv2) ? moved2 : INVALID_KEY;
        cnt = nv2;
    } else {
        cnt += nv;
    }
}

__device__ __forceinline__ void final_flush(unsigned long long& L, unsigned long long& P,
                                            int cnt, bool first, int lane) {
    if (cnt > 0) {
        bitonic_sort32(P, lane);
        if (first) {
            L = P;
        } else {
            unsigned long long brev = shfl_xor64(P, 31);
            L = (L < brev) ? L : brev;
            bitonic_merge32(L, lane);
        }
    }
}

// one CTA (2 warps) per atom pair; each warp scans interleaved halves
__global__ void __launch_bounds__(64)
radius_graph_kernel(const float* __restrict__ pos,
                    const int* __restrict__ batch,
                    float* __restrict__ out,
                    int N) {
    const int i0 = 2 * (int)blockIdx.x;
    if (i0 >= N) return;
    const int i1 = i0 + 1;
    const bool has1 = (i1 < N);
    const int wid = (int)(threadIdx.x >> 5);   // 0 or 1
    const int lane = threadIdx.x & 31;
    const int nk = N * KNB;

    const float x0 = pos[3 * i0 + 0], y0 = pos[3 * i0 + 1], z0 = pos[3 * i0 + 2];
    const float sq0 = sumsq_xla(x0, y0, z0);
    const int b0 = batch[i0];

    float x1 = x0, y1 = y0, z1 = z0, sq1 = sq0;
    int b1 = b0;
    if (has1) {
        x1 = pos[3 * i1 + 0]; y1 = pos[3 * i1 + 1]; z1 = pos[3 * i1 + 2];
        sq1 = sumsq_xla(x1, y1, z1);
        b1 = batch[i1];
    }

    // LO = first index of molecule b0; HI = one past last of molecule b1
    int LO, HI;
    {
        int l = 0, r = N;
        while (l < r) { int m = (l + r) >> 1; if (batch[m] < b0) l = m + 1; else r = m; }
        LO = l;
    }
    {
        int l = LO, r = N;
        while (l < r) { int m = (l + r) >> 1; if (batch[m] <= b1) l = m + 1; else r = m; }
        HI = l;
    }
    int hi0 = (b0 == b1) ? HI : i1;   // batch sorted: split exactly at i1
    int lo1 = (b0 == b1) ? LO : i1;

    unsigned long long L0 = INVALID_KEY, L1 = INVALID_KEY;
    unsigned long long P0 = INVALID_KEY, P1 = INVALID_KEY;
    unsigned long long th0 = INVALID_KEY, th1 = INVALID_KEY;
    int cnt0 = 0, cnt1 = 0;
    bool first0 = true, first1 = true;

    const int per = (HI - LO + 31) >> 5;
    for (int t = wid; t < per; t += 2) {       // interleaved halves per warp
        int j = LO + lane + (t << 5);
        unsigned long long key0 = INVALID_KEY, key1 = INVALID_KEY;
        if (j < HI) {
            float xj = pos[3 * j + 0];
            float yj = pos[3 * j + 1];
            float zj = pos[3 * j + 2];
            float sqj = sumsq_xla(xj, yj, zj);
            if (j < hi0 && j != i0) {
                float dot = __fmaf_rn(z0, zj, __fmaf_rn(y0, yj, __fmul_rn(x0, xj)));
                float d2 = __fsub_rn(__fadd_rn(sq0, sqj), __fmul_rn(2.0f, dot));
                float dist = __fsqrt_rn(fmaxf(d2, 0.0f));
                if (dist <= CUTOFF) {
                    unsigned long long k64 =
                        (((unsigned long long)__float_as_uint(dist)) << 32) | (unsigned int)j;
                    if (k64 < th0) key0 = k64;
                }
            }
            if (has1 && j >= lo1 && j != i1) {
                float dot = __fmaf_rn(z1, zj, __fmaf_rn(y1, yj, __fmul_rn(x1, xj)));
                float d2 = __fsub_rn(__fadd_rn(sq1, sqj), __fmul_rn(2.0f, dot));
                float dist = __fsqrt_rn(fmaxf(d2, 0.0f));
                if (dist <= CUTOFF) {
                    unsigned long long k64 =
                        (((unsigned long long)__float_as_uint(dist)) << 32) | (unsigned int)j;
                    if (k64 < th1) key1 = k64;
                }
            }
        }
        unsigned bal0 = __ballot_sync(FULLMASK, key0 != INVALID_KEY);
        unsigned bal1 = __ballot_sync(FULLMASK, key1 != INVALID_KEY);
        if (bal0) accum(L0, P0, cnt0, th0, first0, key0, bal0, lane);
        if (bal1) accum(L1, P1, cnt1, th1, first1, key1, bal1, lane);
    }
    final_flush(L0, P0, cnt0, first0, lane);
    final_flush(L1, P1, cnt1, first1, lane);

    // cross-warp merge: each warp ends owning one atom's final list
    __shared__ unsigned long long buf[2][32];
    if (wid == 0) buf[1][lane] = L1;   // give my atom-1 half to warp 1
    else          buf[0][lane] = L0;   // give my atom-0 half to warp 0
    __syncthreads();

    unsigned long long mine  = (wid == 0) ? L0 : L1;
    unsigned long long other = buf[wid][lane];
    unsigned long long orev = shfl_xor64(other, 31);   // reverse -> descending
    mine = (mine < orev) ? mine : orev;                // bitonic
    bitonic_merge32(mine, lane);                       // final sorted top-32

    const int ia = (wid == 0) ? i0 : i1;
    if (wid == 1 && !has1) return;
    const float xa = (wid == 0) ? x0 : x1;
    const float ya = (wid == 0) ? y0 : y1;
    const float za = (wid == 0) ? z0 : z1;

    const bool valid = (mine != INVALID_KEY);
    const int j = valid ? (int)(unsigned int)(mine & 0xFFFFFFFFull) : ia;
    const int e = ia * KNB + lane;
    float vx = 0.0f, vy = 0.0f, vz = 0.0f;
    if (valid) {
        vx = __fsub_rn(pos[3 * j + 0], xa);
        vy = __fsub_rn(pos[3 * j + 1], ya);
        vz = __fsub_rn(pos[3 * j + 2], za);
    }
    out[e]                  = (float)ia;           // src
    out[nk + e]             = (float)j;            // dst
    out[2 * nk + 3 * e + 0] = vx;                  // edge_vec
    out[2 * nk + 3 * e + 1] = vy;
    out[2 * nk + 3 * e + 2] = vz;
    out[5 * nk + e]         = valid ? 1.0f : 0.0f; // mask
}

extern "C" void kernel_launch(void* const* d_in, const int* in_sizes, int n_in,
                              void* d_out, int out_size) {
    const float* pos = (const float*)d_in[0];
    const int* batch = (const int*)d_in[1];
    float* out = (float*)d_out;
    int N = in_sizes[1];            // batch has one entry per atom
    (void)n_in; (void)out_size;

    int blocks = (N + 1) / 2;       // one 2-warp CTA per atom pair
    radius_graph_kernel<<<blocks, 64>>>(pos, batch, out, N);
}

// round 9
// speedup vs baseline: 1.0976x; 1.0762x over previous
#include <cuda_runtime.h>
#include <cuda_bf16.h>

#define KNB 32
#define MAXN 8192
#define INVALID_KEY 0xFFFFFFFFFFFFFFFFull
#define FULLMASK 0xFFFFFFFFu

// exact d2 threshold: dist<=5.0 with dist=__fsqrt_rn(d2)  <=>  d2 <= 25+2^-19
#define D2_THRESH_BITS 0x41C80001u

// XLA-matching sum of squares: rn(rn(rn(x^2)+rn(y^2))+rn(z^2)), NO fma fusion
__device__ __forceinline__ float sumsq_xla(float x, float y, float z) {
    return __fadd_rn(__fadd_rn(__fmul_rn(x, x), __fmul_rn(y, y)), __fmul_rn(z, z));
}

__device__ float4 g_psq[MAXN];   // {x, y, z, sumsq}

__global__ void prep_kernel(const float* __restrict__ pos, int N) {
    int i = blockIdx.x * blockDim.x + threadIdx.x;
    if (i < N && i < MAXN) {
        float x = pos[3 * i + 0];
        float y = pos[3 * i + 1];
        float z = pos[3 * i + 2];
        g_psq[i] = make_float4(x, y, z, sumsq_xla(x, y, z));
    }
}

__device__ __forceinline__ unsigned long long shfl_xor64(unsigned long long v, int m) {
    return __shfl_xor_sync(FULLMASK, v, m);
}
__device__ __forceinline__ unsigned long long shfl_idx64(unsigned long long v, int s) {
    return __shfl_sync(FULLMASK, v, s);
}

// full bitonic sort of 32 keys (one per lane), ascending by lane
__device__ __forceinline__ void bitonic_sort32(unsigned long long& v, int lane) {
#pragma unroll
    for (int k = 2; k <= 32; k <<= 1) {
#pragma unroll
        for (int j = k >> 1; j > 0; j >>= 1) {
            unsigned long long o = shfl_xor64(v, j);
            bool up = ((lane & k) == 0);
            bool takeMin = (((lane & j) == 0) == up);
            if ((o < v) == takeMin) v = o;
        }
    }
}

// bitonic merge (input bitonic), sorts ascending by lane
__device__ __forceinline__ void bitonic_merge32(unsigned long long& v, int lane) {
#pragma unroll
    for (int j = 16; j > 0; j >>= 1) {
        unsigned long long o = shfl_xor64(v, j);
        bool takeMin = ((lane & j) == 0);
        if ((o < v) == takeMin) v = o;
    }
}

// accumulate ballot'd candidates into compaction buffer P; flush into L when full
__device__ __forceinline__ void accum(unsigned long long& L, unsigned long long& P,
                                      int& cnt, unsigned long long& thresh, bool& first,
                                      unsigned long long key, unsigned bal, int lane) {
    int nv = __popc(bal);
    int space = 32 - cnt;
    int r = lane - cnt;
    unsigned src = __fns(bal, 0, r + 1);
    unsigned long long moved = shfl_idx64(key, (int)(src & 31u));
    if (r >= 0 && r < nv && r < space) P = moved;

    if (nv >= space) {
        bitonic_sort32(P, lane);
        if (first) {
            L = P; first = false;
        } else {
            unsigned long long brev = shfl_xor64(P, 31);
            L = (L < brev) ? L : brev;
            bitonic_merge32(L, lane);
        }
        thresh = shfl_idx64(L, 31);
        int nv2 = nv - space;
        unsigned src2 = __fns(bal, 0, lane + space + 1);
        unsigned long long moved2 = shfl_idx64(key, (int)(src2 & 31u));
        P = (lane < nv2) ? moved2 : INVALID_KEY;
        cnt = nv2;
    } else {
        cnt += nv;
    }
}

__device__ __forceinline__ void final_flush(unsigned long long& L, unsigned long long& P,
                                            int cnt, bool first, int lane) {
    if (cnt > 0) {
        bitonic_sort32(P, lane);
        if (first) {
            L = P;
        } else {
            unsigned long long brev = shfl_xor64(P, 31);
            L = (L < brev) ? L : brev;
            bitonic_merge32(L, lane);
        }
    }
}

__global__ void __launch_bounds__(128)
radius_graph_kernel(const int* __restrict__ batch,
                    float* __restrict__ out,
                    int N) {
    int w = (int)((blockIdx.x * blockDim.x + threadIdx.x) >> 5);
    int lane = threadIdx.x & 31;
    const int i0 = 2 * w;
    if (i0 >= N) return;
    const int i1 = i0 + 1;
    const bool has1 = (i1 < N);
    const int nk = N * KNB;
    const float D2T = __uint_as_float(D2_THRESH_BITS);

    const float4 p0 = g_psq[i0];
    const float x0 = p0.x, y0 = p0.y, z0 = p0.z, sq0 = p0.w;
    const int b0 = batch[i0];

    float x1 = x0, y1 = y0, z1 = z0, sq1 = sq0;
    int b1 = b0;
    if (has1) {
        float4 p1 = g_psq[i1];
        x1 = p1.x; y1 = p1.y; z1 = p1.z; sq1 = p1.w;
        b1 = batch[i1];
    }

    // LO = first index of molecule b0; HI = one past last of molecule b1
    int LO, HI;
    {
        int l = 0, r = N;
        while (l < r) { int m = (l + r) >> 1; if (batch[m] < b0) l = m + 1; else r = m; }
        LO = l;
    }
    {
        int l = LO, r = N;
        while (l < r) { int m = (l + r) >> 1; if (batch[m] <= b1) l = m + 1; else r = m; }
        HI = l;
    }
    int hi0 = (b0 == b1) ? HI : i1;   // batch sorted: split exactly at i1
    int lo1 = (b0 == b1) ? LO : i1;

    unsigned long long L0 = INVALID_KEY, L1 = INVALID_KEY;
    unsigned long long P0 = INVALID_KEY, P1 = INVALID_KEY;
    unsigned long long th0 = INVALID_KEY, th1 = INVALID_KEY;
    int cnt0 = 0, cnt1 = 0;
    bool first0 = true, first1 = true;

    const int per = (HI - LO + 31) >> 5;
    for (int t = 0; t < per; t++) {
        int j = LO + lane + (t << 5);
        unsigned long long key0 = INVALID_KEY, key1 = INVALID_KEY;
        if (j < HI) {
            float4 pj = g_psq[j];
            const float xj = pj.x, yj = pj.y, zj = pj.z, sqj = pj.w;
            if (j < hi0 && j != i0) {
                float dot = __fmaf_rn(z0, zj, __fmaf_rn(y0, yj, __fmul_rn(x0, xj)));
                float d2 = __fsub_rn(__fadd_rn(sq0, sqj), __fmul_rn(2.0f, dot));
                if (d2 <= D2T) {   // exact equivalent of dist<=5.0; sqrt only if passed
                    float dist = __fsqrt_rn(fmaxf(d2, 0.0f));
                    unsigned long long k64 =
                        (((unsigned long long)__float_as_uint(dist)) << 32) | (unsigned int)j;
                    if (k64 < th0) key0 = k64;
                }
            }
            if (has1 && j >= lo1 && j != i1) {
                float dot = __fmaf_rn(z1, zj, __fmaf_rn(y1, yj, __fmul_rn(x1, xj)));
                float d2 = __fsub_rn(__fadd_rn(sq1, sqj), __fmul_rn(2.0f, dot));
                if (d2 <= D2T) {
                    float dist = __fsqrt_rn(fmaxf(d2, 0.0f));
                    unsigned long long k64 =
                        (((unsigned long long)__float_as_uint(dist)) << 32) | (unsigned int)j;
                    if (k64 < th1) key1 = k64;
                }
            }
        }
        unsigned bal0 = __ballot_sync(FULLMASK, key0 != INVALID_KEY);
        unsigned bal1 = __ballot_sync(FULLMASK, key1 != INVALID_KEY);
        if (bal0) accum(L0, P0, cnt0, th0, first0, key0, bal0, lane);
        if (bal1) accum(L1, P1, cnt1, th1, first1, key1, bal1, lane);
    }
    final_flush(L0, P0, cnt0, first0, lane);
    final_flush(L1, P1, cnt1, first1, lane);

    // lane k owns output slot k: k-th nearest neighbor (exact top_k order)
    {
        const bool valid = (L0 != INVALID_KEY);
        const int j = valid ? (int)(unsigned int)(L0 & 0xFFFFFFFFull) : i0;
        const int e = i0 * KNB + lane;
        float vx = 0.0f, vy = 0.0f, vz = 0.0f;
        if (valid) {
            float4 pj = g_psq[j];
            vx = __fsub_rn(pj.x, x0);
            vy = __fsub_rn(pj.y, y0);
            vz = __fsub_rn(pj.z, z0);
        }
        out[e]                  = (float)i0;
        out[nk + e]             = (float)j;
        out[2 * nk + 3 * e + 0] = vx;
        out[2 * nk + 3 * e + 1] = vy;
        out[2 * nk + 3 * e + 2] = vz;
        out[5 * nk + e]         = valid ? 1.0f : 0.0f;
    }
    if (has1) {
        const bool valid = (L1 != INVALID_KEY);
        const int j = valid ? (int)(unsigned int)(L1 & 0xFFFFFFFFull) : i1;
        const int e = i1 * KNB + lane;
        float vx = 0.0f, vy = 0.0f, vz = 0.0f;
        if (valid) {
            float4 pj = g_psq[j];
            vx = __fsub_rn(pj.x, x1);
            vy = __fsub_rn(pj.y, y1);
            vz = __fsub_rn(pj.z, z1);
        }
        out[e]                  = (float)i1;
        out[nk + e]             = (float)j;
        out[2 * nk + 3 * e + 0] = vx;
        out[2 * nk + 3 * e + 1] = vy;
        out[2 * nk + 3 * e + 2] = vz;
        out[5 * nk + e]         = valid ? 1.0f : 0.0f;
    }
}

extern "C" void kernel_launch(void* const* d_in, const int* in_sizes, int n_in,
                              void* d_out, int out_size) {
    const float* pos = (const float*)d_in[0];
    const int* batch = (const int*)d_in[1];
    float* out = (float*)d_out;
    int N = in_sizes[1];            // batch has one entry per atom
    (void)n_in; (void)out_size;

    prep_kernel<<<(N + 127) / 128, 128>>>(pos, N);

    int nwarps = (N + 1) / 2;       // two atoms per warp
    const int warpsPerBlock = 4;    // 128 threads
    int blocks = (nwarps + warpsPerBlock - 1) / warpsPerBlock;
    radius_graph_kernel<<<blocks, warpsPerBlock * 32>>>(batch, out, N);
}

// round 10
// speedup vs baseline: 1.3636x; 1.2424x over previous
#include <cuda_runtime.h>
#include <cuda_bf16.h>

#define KNB 32
#define INVALID_KEY 0xFFFFFFFFFFFFFFFFull
#define FULLMASK 0xFFFFFFFFu
// exact d2 threshold: dist<=5.0 with dist=__fsqrt_rn(d2)  <=>  d2 <= 25+2^-19
#define D2_THRESH_BITS 0x41C80001u

typedef unsigned long long u64;

// XLA-matching sum of squares: rn(rn(rn(x^2)+rn(y^2))+rn(z^2)), NO fma fusion
__device__ __forceinline__ float sumsq_xla(float x, float y, float z) {
    return __fadd_rn(__fadd_rn(__fmul_rn(x, x), __fmul_rn(y, y)), __fmul_rn(z, z));
}

__device__ __forceinline__ u64 shfl_xor64(u64 v, int m) { return __shfl_xor_sync(FULLMASK, v, m); }
__device__ __forceinline__ u64 shfl_idx64(u64 v, int s) { return __shfl_sync(FULLMASK, v, s); }

// warp-parallel 32-ary search. upper=false: first idx with batch[idx] >= key
// upper=true: first idx with batch[idx] > key. Answer in [0, N].
__device__ __forceinline__ int warp_bound(const int* __restrict__ batch, int N,
                                          int key, int lane, bool upper) {
    int l = 0, w = N;
    while (w > 0) {
        int step = (w + 31) >> 5;
        int off = lane * step;
        bool in = off < w;
        int m = l + (in ? off : 0);
        int bv = batch[m];
        bool cond = in && (upper ? (bv <= key) : (bv < key));
        unsigned bal = __ballot_sync(FULLMASK, cond);
        int c = __popc(bal);
        if (c == 0) { w = 0; }
        else {
            int newl = l + (c - 1) * step + 1;
            int ub = (c * step < w) ? (l + c * step) : (l + w);
            w = ub - newl;
            l = newl;
        }
    }
    return l;
}

// full bitonic sort of 32 keys, ascending by lane
__device__ __forceinline__ void bitonic_sort32(u64& v, int lane) {
#pragma unroll
    for (int k = 2; k <= 32; k <<= 1) {
#pragma unroll
        for (int j = k >> 1; j > 0; j >>= 1) {
            u64 o = shfl_xor64(v, j);
            bool takeMin = (((lane & j) == 0) == ((lane & k) == 0));
            if ((o < v) == takeMin) v = o;
        }
    }
}

// two independent sorts interleaved (2x ILP on the shfl chain)
__device__ __forceinline__ void bitonic_sort32_pair(u64& a, u64& b, int lane) {
#pragma unroll
    for (int k = 2; k <= 32; k <<= 1) {
#pragma unroll
        for (int j = k >> 1; j > 0; j >>= 1) {
            u64 oa = shfl_xor64(a, j);
            u64 ob = shfl_xor64(b, j);
            bool takeMin = (((lane & j) == 0) == ((lane & k) == 0));
            if ((oa < a) == takeMin) a = oa;
            if ((ob < b) == takeMin) b = ob;
        }
    }
}

// bitonic merge (input bitonic), ascending by lane
__device__ __forceinline__ void bitonic_merge32(u64& v, int lane) {
#pragma unroll
    for (int j = 16; j > 0; j >>= 1) {
        u64 o = shfl_xor64(v, j);
        bool takeMin = ((lane & j) == 0);
        if ((o < v) == takeMin) v = o;
    }
}

// flush 64-deep buffer (A,B | cnt valid) into sorted top-32 L
__device__ __forceinline__ void flush64(u64& L, u64& A, u64& B, int cnt,
                                        bool& first, u64& thresh, int lane) {
    if (cnt == 0) return;
    u64 C;
    if (cnt <= 32) {
        bitonic_sort32(A, lane);
        C = A;
    } else {
        bitonic_sort32_pair(A, B, lane);
        u64 brev = shfl_xor64(B, 31);
        C = (A < brev) ? A : brev;
        bitonic_merge32(C, lane);
    }
    if (first) { L = C; first = false; }
    else {
        u64 crev = shfl_xor64(C, 31);
        L = (L < crev) ? L : crev;
        bitonic_merge32(L, lane);
    }
    thresh = shfl_idx64(L, 31);
    A = INVALID_KEY; B = INVALID_KEY;
}

// route ballot'd candidates into 64-deep buffer; flush-first on overflow (rare)
__device__ __forceinline__ void accum64(u64& L, u64& A, u64& B, int& cnt, u64& thresh,
                                        bool& first, u64 key, unsigned bal, int lane) {
    int nv = __popc(bal);
    if (cnt + nv > 64) { flush64(L, A, B, cnt, first, thresh, lane); cnt = 0; }
    if (cnt < 32) {
        int rA = lane - cnt;
        unsigned srcA = __fns(bal, 0, rA + 1);
        u64 mv = shfl_idx64(key, (int)(srcA & 31u));
        if (rA >= 0 && rA < nv) A = mv;
    }
    if (cnt + nv > 32) {
        int rB = lane + 32 - cnt;
        unsigned srcB = __fns(bal, 0, rB + 1);
        u64 mv = shfl_idx64(key, (int)(srcB & 31u));
        if (rB >= 0 && rB < nv) B = mv;
    }
    cnt += nv;
}

__global__ void __launch_bounds__(128)
radius_graph_kernel(const float* __restrict__ pos,
                    const int* __restrict__ batch,
                    float* __restrict__ out,
                    int N) {
    int w = (int)((blockIdx.x * blockDim.x + threadIdx.x) >> 5);
    int lane = threadIdx.x & 31;
    const int i0 = 2 * w;
    if (i0 >= N) return;
    const int i1 = i0 + 1;
    const bool has1 = (i1 < N);
    const int nk = N * KNB;
    const float D2T = __uint_as_float(D2_THRESH_BITS);

    const float x0 = pos[3 * i0 + 0], y0 = pos[3 * i0 + 1], z0 = pos[3 * i0 + 2];
    const float sq0 = sumsq_xla(x0, y0, z0);
    const int b0 = batch[i0];

    float x1 = x0, y1 = y0, z1 = z0, sq1 = sq0;
    int b1 = b0;
    if (has1) {
        x1 = pos[3 * i1 + 0]; y1 = pos[3 * i1 + 1]; z1 = pos[3 * i1 + 2];
        sq1 = sumsq_xla(x1, y1, z1);
        b1 = batch[i1];
    }

    // molecule range: warp-parallel 32-ary search (4 dependent loads, not 13)
    const int LO = warp_bound(batch, N, b0, lane, false);
    const int HI = warp_bound(batch, N, b1, lane, true);
    const int hi0 = (b0 == b1) ? HI : i1;   // batch sorted: split exactly at i1
    const int lo1 = (b0 == b1) ? LO : i1;

    u64 L0 = INVALID_KEY, L1 = INVALID_KEY;
    u64 A0 = INVALID_KEY, B0 = INVALID_KEY, A1 = INVALID_KEY, B1 = INVALID_KEY;
    u64 th0 = INVALID_KEY, th1 = INVALID_KEY;
    int cnt0 = 0, cnt1 = 0;
    bool first0 = true, first1 = true;

    const int per = (HI - LO + 31) >> 5;
    for (int t = 0; t < per; t++) {
        int j = LO + lane + (t << 5);
        u64 key0 = INVALID_KEY, key1 = INVALID_KEY;
        if (j < HI) {
            float xj = pos[3 * j + 0];
            float yj = pos[3 * j + 1];
            float zj = pos[3 * j + 2];
            float sqj = sumsq_xla(xj, yj, zj);
            if (j < hi0 && j != i0) {
                float dot = __fmaf_rn(z0, zj, __fmaf_rn(y0, yj, __fmul_rn(x0, xj)));
                float d2 = __fsub_rn(__fadd_rn(sq0, sqj), __fmul_rn(2.0f, dot));
                if (d2 <= D2T) {   // exact equivalent of dist<=5.0
                    float dist = __fsqrt_rn(fmaxf(d2, 0.0f));
                    u64 k64 = (((u64)__float_as_uint(dist)) << 32) | (unsigned int)j;
                    if (k64 < th0) key0 = k64;
                }
            }
            if (has1 && j >= lo1 && j != i1) {
                float dot = __fmaf_rn(z1, zj, __fmaf_rn(y1, yj, __fmul_rn(x1, xj)));
                float d2 = __fsub_rn(__fadd_rn(sq1, sqj), __fmul_rn(2.0f, dot));
                if (d2 <= D2T) {
                    float dist = __fsqrt_rn(fmaxf(d2, 0.0f));
                    u64 k64 = (((u64)__float_as_uint(dist)) << 32) | (unsigned int)j;
                    if (k64 < th1) key1 = k64;
                }
            }
        }
        unsigned bal0 = __ballot_sync(FULLMASK, key0 != INVALID_KEY);
        unsigned bal1 = __ballot_sync(FULLMASK, key1 != INVALID_KEY);
        if (bal0) accum64(L0, A0, B0, cnt0, th0, first0, key0, bal0, lane);
        if (bal1) accum64(L1, A1, B1, cnt1, th1, first1, key1, bal1, lane);
    }

    // final flush. Common case: both atoms need one sort32 -> interleave them.
    if (first0 && first1 && cnt0 <= 32 && cnt1 <= 32) {
        bitonic_sort32_pair(A0, A1, lane);
        if (cnt0 > 0) L0 = A0;
        if (cnt1 > 0) L1 = A1;
    } else {
        flush64(L0, A0, B0, cnt0, first0, th0, lane);
        flush64(L1, A1, B1, cnt1, first1, th1, lane);
    }

    // lane k owns output slot k: k-th nearest neighbor (exact top_k order)
    {
        const bool valid = (L0 != INVALID_KEY);
        const int j = valid ? (int)(unsigned int)(L0 & 0xFFFFFFFFull) : i0;
        const int e = i0 * KNB + lane;
        float vx = 0.0f, vy = 0.0f, vz = 0.0f;
        if (valid) {
            vx = __fsub_rn(pos[3 * j + 0], x0);
            vy = __fsub_rn(pos[3 * j + 1], y0);
            vz = __fsub_rn(pos[3 * j + 2], z0);
        }
        out[e]                  = (float)i0;
        out[nk + e]             = (float)j;
        out[2 * nk + 3 * e + 0] = vx;
        out[2 * nk + 3 * e + 1] = vy;
        out[2 * nk + 3 * e + 2] = vz;
        out[5 * nk + e]         = valid ? 1.0f : 0.0f;
    }
    if (has1) {
        const bool valid = (L1 != INVALID_KEY);
        const int j = valid ? (int)(unsigned int)(L1 & 0xFFFFFFFFull) : i1;
        const int e = i1 * KNB + lane;
        float vx = 0.0f, vy = 0.0f, vz = 0.0f;
        if (valid) {
            vx = __fsub_rn(pos[3 * j + 0], x1);
            vy = __fsub_rn(pos[3 * j + 1], y1);
            vz = __fsub_rn(pos[3 * j + 2], z1);
        }
        out[e]                  = (float)i1;
        out[nk + e]             = (float)j;
        out[2 * nk + 3 * e + 0] = vx;
        out[2 * nk + 3 * e + 1] = vy;
        out[2 * nk + 3 * e + 2] = vz;
        out[5 * nk + e]         = valid ? 1.0f : 0.0f;
    }
}

extern "C" void kernel_launch(void* const* d_in, const int* in_sizes, int n_in,
                              void* d_out, int out_size) {
    const float* pos = (const float*)d_in[0];
    const int* batch = (const int*)d_in[1];
    float* out = (float*)d_out;
    int N = in_sizes[1];            // batch has one entry per atom
    (void)n_in; (void)out_size;

    int nwarps = (N + 1) / 2;       // two atoms per warp
    const int warpsPerBlock = 4;    // 128 threads
    int blocks = (nwarps + warpsPerBlock - 1) / warpsPerBlock;
    radius_graph_kernel<<<blocks, warpsPerBlock * 32>>>(pos, batch, out, N);
}

// round 11
// speedup vs baseline: 1.5254x; 1.1186x over previous
#include <cuda_runtime.h>
#include <cuda_bf16.h>

#define KNB 32
#define INVALID_KEY 0xFFFFFFFFFFFFFFFFull
#define FULLMASK 0xFFFFFFFFu
// exact d2 threshold: dist<=5.0 with dist=__fsqrt_rn(d2)  <=>  d2 <= 25+2^-19
#define D2_THRESH_BITS 0x41C80001u

typedef unsigned long long u64;

// XLA-matching sum of squares: rn(rn(rn(x^2)+rn(y^2))+rn(z^2)), NO fma fusion
__device__ __forceinline__ float sumsq_xla(float x, float y, float z) {
    return __fadd_rn(__fadd_rn(__fmul_rn(x, x), __fmul_rn(y, y)), __fmul_rn(z, z));
}

__device__ __forceinline__ u64 shfl_xor64(u64 v, int m) { return __shfl_xor_sync(FULLMASK, v, m); }
__device__ __forceinline__ u64 shfl_idx64(u64 v, int s) { return __shfl_sync(FULLMASK, v, s); }

// warp-parallel 32-ary search. upper=false: first idx with batch[idx] >= key
// upper=true: first idx with batch[idx] > key.
__device__ __forceinline__ int warp_bound(const int* __restrict__ batch, int N,
                                          int key, int lane, bool upper) {
    int l = 0, w = N;
    while (w > 0) {
        int step = (w + 31) >> 5;
        int off = lane * step;
        bool in = off < w;
        int m = l + (in ? off : 0);
        int bv = batch[m];
        bool cond = in && (upper ? (bv <= key) : (bv < key));
        unsigned bal = __ballot_sync(FULLMASK, cond);
        int c = __popc(bal);
        if (c == 0) { w = 0; }
        else {
            int newl = l + (c - 1) * step + 1;
            int ub = (c * step < w) ? (l + c * step) : (l + w);
            w = ub - newl;
            l = newl;
        }
    }
    return l;
}

// full bitonic sort of 32 keys, ascending by lane
__device__ __forceinline__ void bitonic_sort32(u64& v, int lane) {
#pragma unroll
    for (int k = 2; k <= 32; k <<= 1) {
#pragma unroll
        for (int j = k >> 1; j > 0; j >>= 1) {
            u64 o = shfl_xor64(v, j);
            bool takeMin = (((lane & j) == 0) == ((lane & k) == 0));
            if ((o < v) == takeMin) v = o;
        }
    }
}

// two independent sorts interleaved (2x ILP on the shfl chain)
__device__ __forceinline__ void bitonic_sort32_pair(u64& a, u64& b, int lane) {
#pragma unroll
    for (int k = 2; k <= 32; k <<= 1) {
#pragma unroll
        for (int j = k >> 1; j > 0; j >>= 1) {
            u64 oa = shfl_xor64(a, j);
            u64 ob = shfl_xor64(b, j);
            bool takeMin = (((lane & j) == 0) == ((lane & k) == 0));
            if ((oa < a) == takeMin) a = oa;
            if ((ob < b) == takeMin) b = ob;
        }
    }
}

// bitonic merge (input bitonic), ascending by lane
__device__ __forceinline__ void bitonic_merge32(u64& v, int lane) {
#pragma unroll
    for (int j = 16; j > 0; j >>= 1) {
        u64 o = shfl_xor64(v, j);
        bool takeMin = ((lane & j) == 0);
        if ((o < v) == takeMin) v = o;
    }
}

// insert key k into sorted-ascending L (drops old max). No-op if k >= L[31].
__device__ __forceinline__ void warp_insert(u64& L, u64 k, int lane) {
    unsigned mlt = __ballot_sync(FULLMASK, L < k);
    int p = __popc(mlt);
    u64 Ls = __shfl_up_sync(FULLMASK, L, 1);
    if (lane >= p) L = (lane == p) ? k : Ls;
}

// rare mid-loop flush: fold the 64-slot smem buffer into L, reset buffer
__device__ __forceinline__ void flush_smem(u64& L, bool& first, u64& thresh,
                                           int& cnt, u64* buf, int lane) {
    __syncwarp();
    u64 A = buf[lane];
    u64 B = buf[32 + lane];
    bitonic_sort32_pair(A, B, lane);
    u64 brev = shfl_xor64(B, 31);
    u64 C = (A < brev) ? A : brev;
    bitonic_merge32(C, lane);              // top-32 of the 64 slots
    if (first) { L = C; first = false; }
    else {
        u64 crev = shfl_xor64(C, 31);
        L = (L < crev) ? L : crev;
        bitonic_merge32(L, lane);
    }
    thresh = shfl_idx64(L, 31);
    buf[lane] = INVALID_KEY;
    buf[32 + lane] = INVALID_KEY;
    __syncwarp();
    cnt = 0;
}

// rare final path when a mid-loop flush happened: merge remaining buffer into L
__device__ __forceinline__ void finalize_merge(u64& L, int cnt, u64 A,
                                               const u64* buf, int lane) {
    if (cnt == 0) return;
    u64 arev = shfl_xor64(A, 31);
    L = (L < arev) ? L : arev;
    bitonic_merge32(L, lane);
    if (cnt > 32) {
        u64 B = buf[32 + lane];
        bitonic_sort32(B, lane);
        u64 brev = shfl_xor64(B, 31);
        L = (L < brev) ? L : brev;
        bitonic_merge32(L, lane);
    }
}

__global__ void __launch_bounds__(128)
radius_graph_kernel(const float* __restrict__ pos,
                    const int* __restrict__ batch,
                    float* __restrict__ out,
                    int N) {
    __shared__ u64 sbuf[4][2][64];
    const int wb = (int)(threadIdx.x >> 5);
    int w = (int)((blockIdx.x * blockDim.x + threadIdx.x) >> 5);
    int lane = threadIdx.x & 31;
    const int i0 = 2 * w;
    if (i0 >= N) return;
    const int i1 = i0 + 1;
    const bool has1 = (i1 < N);
    const int nk = N * KNB;
    const float D2T = __uint_as_float(D2_THRESH_BITS);
    const unsigned lmlt = (1u << lane) - 1u;

    // init buffers
    sbuf[wb][0][lane] = INVALID_KEY; sbuf[wb][0][32 + lane] = INVALID_KEY;
    sbuf[wb][1][lane] = INVALID_KEY; sbuf[wb][1][32 + lane] = INVALID_KEY;
    __syncwarp();

    const float x0 = pos[3 * i0 + 0], y0 = pos[3 * i0 + 1], z0 = pos[3 * i0 + 2];
    const float sq0 = sumsq_xla(x0, y0, z0);
    const int b0 = batch[i0];

    float x1 = x0, y1 = y0, z1 = z0, sq1 = sq0;
    int b1 = b0;
    if (has1) {
        x1 = pos[3 * i1 + 0]; y1 = pos[3 * i1 + 1]; z1 = pos[3 * i1 + 2];
        sq1 = sumsq_xla(x1, y1, z1);
        b1 = batch[i1];
    }

    const int LO = warp_bound(batch, N, b0, lane, false);
    const int HI = warp_bound(batch, N, b1, lane, true);
    const int hi0 = (b0 == b1) ? HI : i1;   // batch sorted: split exactly at i1
    const int lo1 = (b0 == b1) ? LO : i1;

    u64 L0 = INVALID_KEY, L1 = INVALID_KEY;
    u64 th0 = INVALID_KEY, th1 = INVALID_KEY;
    int cnt0 = 0, cnt1 = 0;
    bool first0 = true, first1 = true;

    const int per = (HI - LO + 31) >> 5;
    for (int t = 0; t < per; t++) {
        int j = LO + lane + (t << 5);
        u64 key0 = INVALID_KEY, key1 = INVALID_KEY;
        if (j < HI) {
            float xj = pos[3 * j + 0];
            float yj = pos[3 * j + 1];
            float zj = pos[3 * j + 2];
            float sqj = sumsq_xla(xj, yj, zj);
            if (j < hi0 && j != i0) {
                float dot = __fmaf_rn(z0, zj, __fmaf_rn(y0, yj, __fmul_rn(x0, xj)));
                float d2 = __fsub_rn(__fadd_rn(sq0, sqj), __fmul_rn(2.0f, dot));
                if (d2 <= D2T) {   // exact equivalent of dist<=5.0
                    float dist = __fsqrt_rn(fmaxf(d2, 0.0f));
                    u64 k64 = (((u64)__float_as_uint(dist)) << 32) | (unsigned int)j;
                    if (k64 < th0) key0 = k64;
                }
            }
            if (has1 && j >= lo1 && j != i1) {
                float dot = __fmaf_rn(z1, zj, __fmaf_rn(y1, yj, __fmul_rn(x1, xj)));
                float d2 = __fsub_rn(__fadd_rn(sq1, sqj), __fmul_rn(2.0f, dot));
                if (d2 <= D2T) {
                    float dist = __fsqrt_rn(fmaxf(d2, 0.0f));
                    u64 k64 = (((u64)__float_as_uint(dist)) << 32) | (unsigned int)j;
                    if (k64 < th1) key1 = k64;
                }
            }
        }
        unsigned bal0 = __ballot_sync(FULLMASK, key0 != INVALID_KEY);
        unsigned bal1 = __ballot_sync(FULLMASK, key1 != INVALID_KEY);
        if (bal0) {
            int nv = __popc(bal0);
            if (cnt0 + nv > 64) flush_smem(L0, first0, th0, cnt0, &sbuf[wb][0][0], lane);
            int r = __popc(bal0 & lmlt);
            if (key0 != INVALID_KEY) sbuf[wb][0][cnt0 + r] = key0;
            cnt0 += nv;
        }
        if (bal1) {
            int nv = __popc(bal1);
            if (cnt1 + nv > 64) flush_smem(L1, first1, th1, cnt1, &sbuf[wb][1][0], lane);
            int r = __popc(bal1 & lmlt);
            if (key1 != INVALID_KEY) sbuf[wb][1][cnt1 + r] = key1;
            cnt1 += nv;
        }
    }

    __syncwarp();
    u64 A0 = sbuf[wb][0][lane];
    u64 A1 = sbuf[wb][1][lane];
    bitonic_sort32_pair(A0, A1, lane);   // one interleaved sort covers both atoms

    if (first0 && first1) {
        // dominant path: no mid-loop flush happened for either atom
        if (cnt0 > 0) L0 = A0;
        if (cnt1 > 0) L1 = A1;
        int m0 = cnt0 > 32 ? cnt0 - 32 : 0;
        int m1 = cnt1 > 32 ? cnt1 - 32 : 0;
        int mm = m0 > m1 ? m0 : m1;
        for (int idx = 0; idx < mm; idx++) {      // interleaved tail inserts
            if (idx < m0) warp_insert(L0, sbuf[wb][0][32 + idx], lane);
            if (idx < m1) warp_insert(L1, sbuf[wb][1][32 + idx], lane);
        }
    } else {
        if (first0) {
            if (cnt0 > 0) L0 = A0;
            int m0 = cnt0 > 32 ? cnt0 - 32 : 0;
            for (int idx = 0; idx < m0; idx++)
                warp_insert(L0, sbuf[wb][0][32 + idx], lane);
        } else finalize_merge(L0, cnt0, A0, &sbuf[wb][0][0], lane);
        if (first1) {
            if (cnt1 > 0) L1 = A1;
            int m1 = cnt1 > 32 ? cnt1 - 32 : 0;
            for (int idx = 0; idx < m1; idx++)
                warp_insert(L1, sbuf[wb][1][32 + idx], lane);
        } else finalize_merge(L1, cnt1, A1, &sbuf[wb][1][0], lane);
    }

    // lane k owns output slot k: k-th nearest neighbor (exact top_k order)
    {
        const bool valid = (L0 != INVALID_KEY);
        const int j = valid ? (int)(unsigned int)(L0 & 0xFFFFFFFFull) : i0;
        const int e = i0 * KNB + lane;
        float vx = 0.0f, vy = 0.0f, vz = 0.0f;
        if (valid) {
            vx = __fsub_rn(pos[3 * j + 0], x0);
            vy = __fsub_rn(pos[3 * j + 1], y0);
            vz = __fsub_rn(pos[3 * j + 2], z0);
        }
        out[e]                  = (float)i0;
        out[nk + e]             = (float)j;
        out[2 * nk + 3 * e + 0] = vx;
        out[2 * nk + 3 * e + 1] = vy;
        out[2 * nk + 3 * e + 2] = vz;
        out[5 * nk + e]         = valid ? 1.0f : 0.0f;
    }
    if (has1) {
        const bool valid = (L1 != INVALID_KEY);
        const int j = valid ? (int)(unsigned int)(L1 & 0xFFFFFFFFull) : i1;
        const int e = i1 * KNB + lane;
        float vx = 0.0f, vy = 0.0f, vz = 0.0f;
        if (valid) {
            vx = __fsub_rn(pos[3 * j + 0], x1);
            vy = __fsub_rn(pos[3 * j + 1], y1);
            vz = __fsub_rn(pos[3 * j + 2], z1);
        }
        out[e]                  = (float)i1;
        out[nk + e]             = (float)j;
        out[2 * nk + 3 * e + 0] = vx;
        out[2 * nk + 3 * e + 1] = vy;
        out[2 * nk + 3 * e + 2] = vz;
        out[5 * nk + e]         = valid ? 1.0f : 0.0f;
    }
}

extern "C" void kernel_launch(void* const* d_in, const int* in_sizes, int n_in,
                              void* d_out, int out_size) {
    const float* pos = (const float*)d_in[0];
    const int* batch = (const int*)d_in[1];
    float* out = (float*)d_out;
    int N = in_sizes[1];            // batch has one entry per atom
    (void)n_in; (void)out_size;

    int nwarps = (N + 1) / 2;       // two atoms per warp
    const int warpsPerBlock = 4;    // 128 threads
    int blocks = (nwarps + warpsPerBlock - 1) / warpsPerBlock;
    radius_graph_kernel<<<blocks, warpsPerBlock * 32>>>(pos, batch, out, N);
}